// round 9
// baseline (speedup 1.0000x reference)
#include <cuda_runtime.h>
#include <cuda_bf16.h>

#define HW     8192
#define THRESH 0.5f
#define TX     128      // output tile cols per block
#define TY     64       // output tile rows per block
#define IN_H   72       // h rows per tile (TY + 8 halo)
#define RS     76       // transposed col stride (mult of 4: aligned LDS.128, conflict-free)
#define NTHREADS 256

#define SMEM_BYTES (TX * RS * (int)sizeof(float))   // 38912 B

__device__ __forceinline__ float4 thresh4(float4 v) {
    v.x = (v.x > THRESH) ? v.x : 0.f;
    v.y = (v.y > THRESH) ? v.y : 0.f;
    v.z = (v.z > THRESH) ? v.z : 0.f;
    v.w = (v.w > THRESH) ? v.w : 0.f;
    return v;
}

// encode flag (h==ctr) into sign bit; h >= 0 so -h / -0.0 carries the flag
__device__ __forceinline__ float enc(float h, float ctr) {
    return (h == ctr) ? -h : h;
}

__global__ void __launch_bounds__(NTHREADS, 4)
postprocess_kernel(const float* __restrict__ in, float* __restrict__ out)
{
    extern __shared__ float h_t[];      // [col 0..127][row 0..71], stride RS

    const int bx = blockIdx.x;          // 0..63
    const int by = blockIdx.y;          // 0..127
    const int tid = threadIdx.x;

    const int gr0 = by * TY - 4;        // first h row in global coords

    // -------- Phase A: load + threshold + horizontal 9-max -> transposed h_t
    // 576 tasks, seg-major (t = seg*72 + row) so warp lanes vary by row:
    // STS.32 banks = (const + row) mod 32 -> conflict-free (boundary warps ~2-way).
    for (int t = tid; t < 8 * IN_H; t += NTHREADS) {
        const int seg = t / IN_H;
        const int row = t - seg * IN_H;
        const int gr  = gr0 + row;
        const int cb  = bx * TX + seg * 16;      // first output col of segment
        const float* rp = in + (size_t)gr * HW;

        float4 blk[6];                           // input cols cb-4 .. cb+19
        const bool rin = (unsigned)gr < (unsigned)HW;
        const bool cin = (cb - 4 >= 0) && (cb + 19 < HW);
        if (rin && cin) {
#pragma unroll
            for (int j = 0; j < 6; j++)
                blk[j] = thresh4(*reinterpret_cast<const float4*>(&rp[cb - 4 + 4 * j]));
        } else {
#pragma unroll
            for (int j = 0; j < 6; j++) {
                const int c0 = cb - 4 + 4 * j;
                float4 v = make_float4(0.f, 0.f, 0.f, 0.f);
                if (rin) {
                    if ((unsigned)(c0 + 0) < (unsigned)HW) v.x = rp[c0 + 0];
                    if ((unsigned)(c0 + 1) < (unsigned)HW) v.y = rp[c0 + 1];
                    if ((unsigned)(c0 + 2) < (unsigned)HW) v.z = rp[c0 + 2];
                    if ((unsigned)(c0 + 3) < (unsigned)HW) v.w = rp[c0 + 3];
                }
                blk[j] = thresh4(v);
            }
        }

        float* base = &h_t[(seg * 16) * RS + row];
#pragma unroll
        for (int g = 0; g < 4; g++) {
            const float4 a = blk[g];
            const float4 b = blk[g + 1];   // b is also the center values
            const float4 d = blk[g + 2];
            // suffix maxes of a
            const float s3 = a.w;
            const float s2 = fmaxf(a.z, s3);
            const float s1 = fmaxf(a.y, s2);
            const float s0 = fmaxf(a.x, s1);
            // full max of b
            const float mb = fmaxf(fmaxf(b.x, b.y), fmaxf(b.z, b.w));
            // prefix maxes of d
            const float p0 = d.x;
            const float p1 = fmaxf(p0, d.y);
            const float p2 = fmaxf(p1, d.z);
            const float p3 = fmaxf(p2, d.w);
            const float hx = fmaxf(fmaxf(s0, mb), p0);
            const float hy = fmaxf(fmaxf(s1, mb), p1);
            const float hz = fmaxf(fmaxf(s2, mb), p2);
            const float hw = fmaxf(fmaxf(s3, mb), p3);
            // transposed scalar stores, sign-encoded peak flag
            base[(4 * g + 0) * RS] = enc(hx, b.x);
            base[(4 * g + 1) * RS] = enc(hy, b.y);
            base[(4 * g + 2) * RS] = enc(hz, b.z);
            base[(4 * g + 3) * RS] = enc(hw, b.w);
        }
    }
    __syncthreads();

    // -------- Phase B: vertical 9-max streaming down one column ----------
    // 256 tasks: col 0..127 x strip 0..1 (32 output rows each).
    // Gil-Werman blocks of 8 along rows: re-read amp = 40/32 = 1.25x.
    {
        const int c = tid & 127;            // local output col
        const int s = tid >> 7;             // strip 0/1
        const float* hp = &h_t[c * RS + s * 32];

        float* op = out + (size_t)(by * TY + s * 32) * HW + (size_t)(bx * TX + c);

        // Block 0 (h local rows 0..7): keep raw tail, build suffix of |.|
        float C[8], S[8], rawt[4];
        {
            const float4 u0 = *reinterpret_cast<const float4*>(hp + 0);
            const float4 u1 = *reinterpret_cast<const float4*>(hp + 4);
            C[0]=u0.x; C[1]=u0.y; C[2]=u0.z; C[3]=u0.w;
            C[4]=u1.x; C[5]=u1.y; C[6]=u1.z; C[7]=u1.w;
        }
        rawt[0]=C[4]; rawt[1]=C[5]; rawt[2]=C[6]; rawt[3]=C[7];
        S[7] = fabsf(C[7]);
#pragma unroll
        for (int j = 6; j >= 0; j--) S[j] = fmaxf(fabsf(C[j]), S[j + 1]);

#pragma unroll
        for (int k = 1; k <= 4; k++) {
            const float4 u0 = *reinterpret_cast<const float4*>(hp + 8 * k);
            const float4 u1 = *reinterpret_cast<const float4*>(hp + 8 * k + 4);
            C[0]=u0.x; C[1]=u0.y; C[2]=u0.z; C[3]=u0.w;
            C[4]=u1.x; C[5]=u1.y; C[6]=u1.z; C[7]=u1.w;

            float P = fabsf(C[0]);
#pragma unroll
            for (int i = 0; i < 8; i++) {
                if (i > 0) P = fmaxf(P, fabsf(C[i]));
                const float mp = fmaxf(S[i], P);          // 9-tap vertical max
                const float ctr_s = (i < 4) ? rawt[i] : C[i - 4];
                const float hc = fabsf(ctr_s);
                const bool flag = (__float_as_int(ctr_s) & 0x80000000) != 0;
                const float o = (mp > 0.f && mp == hc && flag) ? mp : 0.f;
                op[(size_t)((k - 1) * 8 + i) * HW] = o;
            }
            rawt[0]=C[4]; rawt[1]=C[5]; rawt[2]=C[6]; rawt[3]=C[7];
            S[7] = fabsf(C[7]);
#pragma unroll
            for (int j = 6; j >= 0; j--) S[j] = fmaxf(fabsf(C[j]), S[j + 1]);
        }
    }
}

extern "C" void kernel_launch(void* const* d_in, const int* in_sizes, int n_in,
                              void* d_out, int out_size)
{
    const float* in = (const float*)d_in[0];
    float* out = (float*)d_out;

    static bool attr_set = false;
    if (!attr_set) {
        cudaFuncSetAttribute(postprocess_kernel,
                             cudaFuncAttributeMaxDynamicSharedMemorySize,
                             SMEM_BYTES);
        attr_set = true;
    }

    dim3 grid(HW / TX, HW / TY);   // 64 x 128
    postprocess_kernel<<<grid, NTHREADS, SMEM_BYTES>>>(in, out);
}

// round 10
// speedup vs baseline: 1.3302x; 1.3302x over previous
#include <cuda_runtime.h>
#include <cuda_bf16.h>

#define HW     8192
#define THRESH 0.5f
#define TX     128      // output tile cols per block
#define TY     64       // output tile rows per block
#define IN_H   72       // h rows per tile (TY + 8 halo)
#define SEG_STRIDE 20   // 16 data + 4 pad floats per 16-col segment (proven R8 layout)
#define H_PAD  164      // floats per h_s row: 8 segs * 20 + 4
#define NTHREADS 256

#define SMEM_BYTES (IN_H * H_PAD * (int)sizeof(float))

__device__ __forceinline__ float2 f2max(float2 a, float2 b) {
    float2 r; r.x = fmaxf(a.x, b.x); r.y = fmaxf(a.y, b.y); return r;
}
__device__ __forceinline__ float2 f2amax(float2 a, float2 b) {   // max(|a|, b)
    float2 r; r.x = fmaxf(fabsf(a.x), b.x); r.y = fmaxf(fabsf(a.y), b.y); return r;
}
__device__ __forceinline__ float2 f2abs(float2 a) {
    float2 r; r.x = fabsf(a.x); r.y = fabsf(a.y); return r;
}

__device__ __forceinline__ float4 thresh4(float4 v) {
    v.x = (v.x > THRESH) ? v.x : 0.f;
    v.y = (v.y > THRESH) ? v.y : 0.f;
    v.z = (v.z > THRESH) ? v.z : 0.f;
    v.w = (v.w > THRESH) ? v.w : 0.f;
    return v;
}

// encode flag (h==ctr) into sign bit; h >= 0 post-threshold, so -h (or -0.0)
// carries the flag and fabsf recovers the magnitude.
__device__ __forceinline__ float enc(float h, float ctr) {
    return (h == ctr) ? -h : h;
}

// epilogue: peak iff vertical max mp equals |s| (its own column's h value)
// AND the sign flag says h == ctr, AND positive.
__device__ __forceinline__ float peak1(float mp, float s) {
    const bool flag = (__float_as_int(s) & 0x80000000) != 0;
    return (mp > 0.f && mp == fabsf(s) && flag) ? mp : 0.f;
}

__global__ void __launch_bounds__(NTHREADS, 4)
postprocess_kernel(const float* __restrict__ in, float* __restrict__ out)
{
    extern __shared__ float h_s[];      // IN_H x H_PAD (segmented layout)

    const int bx = blockIdx.x;          // 0..63
    const int by = blockIdx.y;          // 0..127
    const int tid = threadIdx.x;

    const int gr0 = by * TY - 4;        // first h row in global coords

    // -------- Phase A: load + threshold + horiz 9-max + flag-encode -> h_s
    for (int t = tid; t < IN_H * 8; t += NTHREADS) {
        const int row = t >> 3;
        const int seg = t & 7;
        const int gr  = gr0 + row;
        const int cb  = bx * TX + seg * 16;      // first output col of segment
        const float* rp = in + (size_t)gr * HW;

        float4 blk[6];                           // input cols cb-4 .. cb+19
        const bool rin = (unsigned)gr < (unsigned)HW;
        const bool cin = (cb - 4 >= 0) && (cb + 19 < HW);
        if (rin && cin) {
#pragma unroll
            for (int j = 0; j < 6; j++)
                blk[j] = thresh4(*reinterpret_cast<const float4*>(&rp[cb - 4 + 4 * j]));
        } else {
#pragma unroll
            for (int j = 0; j < 6; j++) {
                const int c0 = cb - 4 + 4 * j;
                float4 v = make_float4(0.f, 0.f, 0.f, 0.f);
                if (rin) {
                    if ((unsigned)(c0 + 0) < (unsigned)HW) v.x = rp[c0 + 0];
                    if ((unsigned)(c0 + 1) < (unsigned)HW) v.y = rp[c0 + 1];
                    if ((unsigned)(c0 + 2) < (unsigned)HW) v.z = rp[c0 + 2];
                    if ((unsigned)(c0 + 3) < (unsigned)HW) v.w = rp[c0 + 3];
                }
                blk[j] = thresh4(v);
            }
        }

        float* hrow = &h_s[row * H_PAD + seg * SEG_STRIDE];
#pragma unroll
        for (int g = 0; g < 4; g++) {
            const float4 a = blk[g];
            const float4 b = blk[g + 1];   // b holds the 4 center values
            const float4 d = blk[g + 2];
            // suffix maxes of a
            const float s3 = a.w;
            const float s2 = fmaxf(a.z, s3);
            const float s1 = fmaxf(a.y, s2);
            const float s0 = fmaxf(a.x, s1);
            // full max of b
            const float mb = fmaxf(fmaxf(b.x, b.y), fmaxf(b.z, b.w));
            // prefix maxes of d
            const float p0 = d.x;
            const float p1 = fmaxf(p0, d.y);
            const float p2 = fmaxf(p1, d.z);
            const float p3 = fmaxf(p2, d.w);
            float4 o;
            o.x = enc(fmaxf(fmaxf(s0, mb), p0), b.x);
            o.y = enc(fmaxf(fmaxf(s1, mb), p1), b.y);
            o.z = enc(fmaxf(fmaxf(s2, mb), p2), b.z);
            o.w = enc(fmaxf(fmaxf(s3, mb), p3), b.w);
            *reinterpret_cast<float4*>(&hrow[4 * g]) = o;
        }
    }
    __syncthreads();

    // -------- Phase B: vertical 9-max (3-block Gil-Werman, |.| chains) ----
    // 256 tasks: (col-pair 0..63) x (16-row strip 0..3). No global re-read:
    // peak flag decoded from the sign bit of the stored (signed) h values.
    {
        const int cp    = tid & 63;
        const int strip = tid >> 6;
        const int c  = cp * 2;              // local output col (even: aligned LDS.64)
        const int r0 = strip * 16;          // local output row base

        const int cofs = (c >> 4) * SEG_STRIDE + (c & 15);
        const float* hp = &h_s[r0 * H_PAD + cofs];

        float* op = out + (size_t)(by * TY + r0) * HW + (size_t)(bx * TX + c);

        // Block A (h local rows 0..7): suffix maxes of |.|; keep raw rows 4..7
        float2 S[8], rawt[4];
        {
            float2 A[8];
#pragma unroll
            for (int j = 0; j < 8; j++)
                A[j] = *reinterpret_cast<const float2*>(&hp[j * H_PAD]);
#pragma unroll
            for (int k = 0; k < 4; k++) rawt[k] = A[4 + k];
            S[7] = f2abs(A[7]);
#pragma unroll
            for (int j = 6; j >= 0; j--) S[j] = f2amax(A[j], S[j + 1]);
        }

        // Stream block B (h rows 8..15): emit out rows 0..7. Keep B raw.
        float2 B[8], P;
#pragma unroll
        for (int i = 0; i < 8; i++) {
            const float2 bi = *reinterpret_cast<const float2*>(&hp[(8 + i) * H_PAD]);
            B[i] = bi;
            P = (i == 0) ? f2abs(bi) : f2amax(bi, P);
            const float2 mp = f2max(S[i], P);          // 9-tap vertical max of |h|
            const float2 cs = (i < 4) ? rawt[i] : B[i - 4];  // signed center h
            float2 o;
            o.x = peak1(mp.x, cs.x);
            o.y = peak1(mp.y, cs.y);
            *reinterpret_cast<float2*>(&op[(size_t)i * HW]) = o;
        }

        // Re-arm: raw tail of B, suffix maxes of |B|
#pragma unroll
        for (int k = 0; k < 4; k++) rawt[k] = B[4 + k];
        S[7] = f2abs(B[7]);
#pragma unroll
        for (int j = 6; j >= 0; j--) S[j] = f2amax(B[j], S[j + 1]);

        // Stream block C (h rows 16..23): emit out rows 8..15.
        float2 Craw[4];
#pragma unroll
        for (int i = 0; i < 8; i++) {
            const float2 ci = *reinterpret_cast<const float2*>(&hp[(16 + i) * H_PAD]);
            if (i < 4) Craw[i] = ci;
            P = (i == 0) ? f2abs(ci) : f2amax(ci, P);
            const float2 mp = f2max(S[i], P);
            const float2 cs = (i < 4) ? rawt[i] : Craw[i - 4];
            float2 o;
            o.x = peak1(mp.x, cs.x);
            o.y = peak1(mp.y, cs.y);
            *reinterpret_cast<float2*>(&op[(size_t)(8 + i) * HW]) = o;
        }
    }
}

extern "C" void kernel_launch(void* const* d_in, const int* in_sizes, int n_in,
                              void* d_out, int out_size)
{
    const float* in = (const float*)d_in[0];
    float* out = (float*)d_out;

    static bool attr_set = false;
    if (!attr_set) {
        cudaFuncSetAttribute(postprocess_kernel,
                             cudaFuncAttributeMaxDynamicSharedMemorySize,
                             SMEM_BYTES);
        attr_set = true;
    }

    dim3 grid(HW / TX, HW / TY);   // 64 x 128
    postprocess_kernel<<<grid, NTHREADS, SMEM_BYTES>>>(in, out);
}